// round 15
// baseline (speedup 1.0000x reference)
#include <cuda_runtime.h>
#include <cuda_fp16.h>
#include <math.h>
#include <stdint.h>

#define B_  8
#define N_  4096
#define D_  1024
#define H_  16
#define DH_ 64
#define M_  (B_ * N_)   // 32768 rows

// ---------------- scratch (static device memory; allocation-free) ----------
__device__ __half g_Wh[(size_t)3 * D_ * D_];     // fp16 Wq|Wk|Wv
__device__ __half g_Qh[(size_t)M_ * D_];         // post-elu Q (fp16)
__device__ __half g_Kh[(size_t)M_ * D_];         // fp16 K (post elu+mask)
__device__ __half g_Vh[(size_t)M_ * D_];         // fp16 V
__device__ __half g_GTh[(size_t)B_ * D_ * D_];   // folded Wo∘kv∘qnorm (fp16)
__device__ float g_qnorm[B_ * D_];
__device__ float g_kv[B_ * H_ * DH_ * DH_];

// =====================  helpers  ===========================================
__device__ __forceinline__ uint32_t smem_addr_u32(const void* p) {
    uint32_t a;
    asm("{ .reg .u64 t; cvta.to.shared.u64 t, %1; cvt.u32.u64 %0, t; }"
        : "=r"(a) : "l"(p));
    return a;
}

__device__ __forceinline__ uint32_t h2_u32(float x, float y) {
    __half2 h = __floats2half2_rn(x, y);
    return *reinterpret_cast<uint32_t*>(&h);
}

__device__ __forceinline__ void sts_b64(uint32_t a, uint32_t x, uint32_t y) {
    asm volatile("st.shared.v2.b32 [%0], {%1, %2};" :: "r"(a), "r"(x), "r"(y) : "memory");
}

__device__ __forceinline__ void sts_b128(uint32_t a, uint4 v) {
    asm volatile("st.shared.v4.b32 [%0], {%1, %2, %3, %4};"
                 :: "r"(a), "r"(v.x), "r"(v.y), "r"(v.z), "r"(v.w) : "memory");
}

// fp16 MMA, fp32 accumulate
__device__ __forceinline__ void mma16816h(float* c, const uint32_t* a, const uint32_t* b) {
    asm volatile(
        "mma.sync.aligned.m16n8k16.row.col.f32.f16.f16.f32 "
        "{%0,%1,%2,%3}, {%4,%5,%6,%7}, {%8,%9}, {%0,%1,%2,%3};"
        : "+f"(c[0]), "+f"(c[1]), "+f"(c[2]), "+f"(c[3])
        : "r"(a[0]), "r"(a[1]), "r"(a[2]), "r"(a[3]), "r"(b[0]), "r"(b[1]));
}

#define LDSM4(r, a)                                                            \
    asm volatile("ldmatrix.sync.aligned.m8n8.x4.shared.b16 {%0,%1,%2,%3}, [%4];" \
        : "=r"((r)[0]), "=r"((r)[1]), "=r"((r)[2]), "=r"((r)[3]) : "r"(a))

#define CP_ASYNC16(dst, src)                                                   \
    asm volatile("cp.async.cg.shared.global [%0], [%1], 16;"                   \
        :: "r"(dst), "l"(src) : "memory")
#define CP_COMMIT()  asm volatile("cp.async.commit_group;" ::: "memory")
#define CP_WAIT1()   asm volatile("cp.async.wait_group 1;" ::: "memory")

// ---------------------------------------------------------------------------
// smem: A 2-stage (10240 B each: 128 rows x 80B); B 3-stage at +20480.
// ---------------------------------------------------------------------------
#define ASTG_ 10240u
#define BBASE_ 20480u
#define BSTG_ 10240u
static constexpr size_t GEMM_SMEM = 2 * 10240 + 3 * 10240;   // 51200 B

// ---------------------------------------------------------------------------
// fp16 HMMA mainloop (fp32 A in global): acc += A @ Bh^T over K=1024.
// A: LDG fp32 prefetch -> cvt fp16 -> STS (2-stage). B: cp.async fp16
// (3-stage). One __syncthreads per stage. 32 MMA/warp/stage.
// ---------------------------------------------------------------------------
__device__ __forceinline__ void gemm_mainloop(
    const float* Ap, const __half* Bp,
    uint32_t sb, uint32_t a_sts, uint32_t b_dst,
    uint32_t a_off, uint32_t b_off, float acc[2][8][4])
{
    float4 pa[4];

#pragma unroll
    for (int st = 0; st < 2; st++) {
        const uint32_t bd = b_dst + (uint32_t)st * BSTG_;
        const __half* g0 = Bp + st * 32;
#pragma unroll
        for (int c = 0; c < 2; c++)
            CP_ASYNC16(bd + c * 16u, g0 + c * 8);
        CP_COMMIT();
    }
#pragma unroll
    for (int i = 0; i < 4; i++)
        pa[i] = *(const float4*)(Ap + (size_t)(i << 5) * D_);
#pragma unroll
    for (int i = 0; i < 4; i++)
        sts_b64(a_sts + (uint32_t)(i * 32 * 80),
                h2_u32(pa[i].x, pa[i].y), h2_u32(pa[i].z, pa[i].w));
#pragma unroll
    for (int i = 0; i < 4; i++)
        pa[i] = *(const float4*)(Ap + 32 + (size_t)(i << 5) * D_);

    int bs = 0;
#pragma unroll 1
    for (int s = 0; s < 32; s++) {
        CP_WAIT1();
        __syncthreads();

        if (s < 31) {
            const uint32_t an = a_sts + (uint32_t)((s + 1) & 1) * ASTG_;
#pragma unroll
            for (int i = 0; i < 4; i++)
                sts_b64(an + (uint32_t)(i * 32 * 80),
                        h2_u32(pa[i].x, pa[i].y), h2_u32(pa[i].z, pa[i].w));
        }
        if (s + 2 < 32) {
            const int k0n = (s + 2) << 5;
#pragma unroll
            for (int i = 0; i < 4; i++)
                pa[i] = *(const float4*)(Ap + k0n + (size_t)(i << 5) * D_);
            const int bs2 = (bs + 2 >= 3) ? bs - 1 : bs + 2;
            const uint32_t bd = b_dst + (uint32_t)bs2 * BSTG_;
#pragma unroll
            for (int c = 0; c < 2; c++)
                CP_ASYNC16(bd + c * 16u, Bp + k0n + c * 8);
        }
        CP_COMMIT();

        const uint32_t ca = sb + (uint32_t)(s & 1) * ASTG_;
        const uint32_t cb = sb + BBASE_ + (uint32_t)bs * BSTG_;
#pragma unroll
        for (int kk = 0; kk < 2; kk++) {
            const uint32_t ko = (uint32_t)kk * 32u;
            uint32_t ah[2][4];
            LDSM4(ah[0], ca + a_off + ko);
            LDSM4(ah[1], ca + a_off + 1280u + ko);
#pragma unroll
            for (int ng = 0; ng < 4; ng++) {
                uint32_t bh4[4];
                LDSM4(bh4, cb + b_off + (uint32_t)ng * 1280u + ko);
                mma16816h(acc[0][2 * ng],     ah[0], bh4);
                mma16816h(acc[0][2 * ng + 1], ah[0], bh4 + 2);
                mma16816h(acc[1][2 * ng],     ah[1], bh4);
                mma16816h(acc[1][2 * ng + 1], ah[1], bh4 + 2);
            }
        }
        bs = (bs + 1 >= 3) ? 0 : bs + 1;
    }
}

// ---------------------------------------------------------------------------
// QKV GEMM (fp32 inputs). MODE 0: plain (V); MODE 1: 1+elu + fused qnorm
// atomics (Q); MODE 2: 1+elu + mask (K).  All outputs fp16.
// ---------------------------------------------------------------------------
template <int MODE>
__global__ void __launch_bounds__(256, 2)
gemm_qkv(const float* __restrict__ A, const __half* __restrict__ Bh,
         const float* __restrict__ bias, const int* __restrict__ mask,
         __half* __restrict__ Ch)
{
    extern __shared__ __align__(16) char smem[];
    const uint32_t sb = smem_addr_u32(smem);
    const int tid  = threadIdx.x;
    const int lane = tid & 31;
    const int wid  = tid >> 5;
    const int warpM = wid & 3;
    const int warpN = wid >> 2;
    const int bm = blockIdx.y << 7;
    const int bn = blockIdx.x << 7;

    const int r0 = tid >> 3;
    const int c4 = tid & 7;
    const float* Ap = A + (size_t)(bm + r0) * D_ + (c4 << 2);
    const uint32_t a_sts = sb + (uint32_t)(r0 * 80 + c4 * 8);

    const int brow = tid >> 1;
    const int bpart = tid & 1;
    const __half* Bp = Bh + (size_t)(bn + brow) * D_ + bpart * 16;
    const uint32_t b_dst = sb + BBASE_ + (uint32_t)(brow * 80 + bpart * 32);

    const uint32_t a_off = (uint32_t)(((lane & 7) + ((lane >> 3) & 1) * 8 + warpM * 32) * 80
                                      + ((lane >> 4) & 1) * 16);
    const uint32_t b_off = (uint32_t)(((lane & 7) + ((lane >> 4) & 1) * 8 + warpN * 64) * 80
                                      + ((lane >> 3) & 1) * 16);

    float acc[2][8][4];
#pragma unroll
    for (int mt = 0; mt < 2; mt++)
#pragma unroll
        for (int nt = 0; nt < 8; nt++)
#pragma unroll
            for (int r = 0; r < 4; r++) acc[mt][nt][r] = 0.f;

    gemm_mainloop(Ap, Bp, sb, a_sts, b_dst, a_off, b_off, acc);

    // ---- epilogue ----
    const int g = lane >> 2, t = lane & 3;
    float cs[8][2];
    if (MODE == 1) {
#pragma unroll
        for (int nt = 0; nt < 8; nt++) { cs[nt][0] = 0.f; cs[nt][1] = 0.f; }
    }

#pragma unroll
    for (int mt = 0; mt < 2; mt++) {
        const int row0 = bm + warpM * 32 + mt * 16 + g;
        const int row1 = row0 + 8;
        int m0 = 0, m1 = 0;
        if (MODE == 2) { m0 = mask[row0]; m1 = mask[row1]; }
#pragma unroll
        for (int nt = 0; nt < 8; nt++) {
            const int col = bn + warpN * 64 + nt * 8 + t * 2;
            const float2 bv2 = *(const float2*)(bias + col);
            float v0 = acc[mt][nt][0] + bv2.x;
            float v1 = acc[mt][nt][1] + bv2.y;
            float v2 = acc[mt][nt][2] + bv2.x;
            float v3 = acc[mt][nt][3] + bv2.y;
            if (MODE == 1 || MODE == 2) {
                v0 = (v0 > 0.f) ? (v0 + 1.f) : expf(v0);
                v1 = (v1 > 0.f) ? (v1 + 1.f) : expf(v1);
                v2 = (v2 > 0.f) ? (v2 + 1.f) : expf(v2);
                v3 = (v3 > 0.f) ? (v3 + 1.f) : expf(v3);
            }
            if (MODE == 2) {
                if (m0) { v0 = 0.f; v1 = 0.f; }
                if (m1) { v2 = 0.f; v3 = 0.f; }
            }
            if (MODE == 1) {
                cs[nt][0] += v0 * v0 + v2 * v2;
                cs[nt][1] += v1 * v1 + v3 * v3;
            }
            *(uint32_t*)(Ch + (size_t)row0 * D_ + col) = h2_u32(v0, v1);
            *(uint32_t*)(Ch + (size_t)row1 * D_ + col) = h2_u32(v2, v3);
        }
    }

    if (MODE == 1) {
        const int b = bm >> 12;
#pragma unroll
        for (int nt = 0; nt < 8; nt++) {
#pragma unroll
            for (int c = 0; c < 2; c++) {
                float s = cs[nt][c];
                s += __shfl_xor_sync(0xffffffffu, s, 4);
                s += __shfl_xor_sync(0xffffffffu, s, 8);
                s += __shfl_xor_sync(0xffffffffu, s, 16);
                if (g == 0) {
                    const int col = bn + warpN * 64 + nt * 8 + t * 2 + c;
                    atomicAdd(&g_qnorm[b * D_ + col], s);
                }
            }
        }
    }
}

// ---------------------------------------------------------------------------
// Output GEMM: out = Qh @ GT_b^T + bo.  A is fp16 in global -> LDG.128
// prefetch -> STS.128 (no conversion).  B via cp.async (identical to QKV).
// ---------------------------------------------------------------------------
__global__ void __launch_bounds__(256, 2)
gemm_out(const __half* __restrict__ A, const float* __restrict__ bias,
         float* __restrict__ C)
{
    extern __shared__ __align__(16) char smem[];
    const uint32_t sb = smem_addr_u32(smem);
    const int tid  = threadIdx.x;
    const int lane = tid & 31;
    const int wid  = tid >> 5;
    const int warpM = wid & 3;
    const int warpN = wid >> 2;
    const int bm = blockIdx.y << 7;
    const int bn = blockIdx.x << 7;

    const __half* Bh = g_GTh + (((size_t)(bm >> 12)) << 20);

    // A: 2 threads per row; thread covers 2 x 16B chunks (32B of the 64B row)
    const int arow = tid >> 1;
    const int aq   = (tid & 1) << 1;     // chunk index 0 or 2
    const __half* Ap = A + (size_t)(bm + arow) * D_ + aq * 8;
    const uint32_t a_sts = sb + (uint32_t)(arow * 80 + aq * 16);

    const int brow = tid >> 1;
    const int bpart = tid & 1;
    const __half* Bp = Bh + (size_t)(bn + brow) * D_ + bpart * 16;
    const uint32_t b_dst = sb + BBASE_ + (uint32_t)(brow * 80 + bpart * 32);

    const uint32_t a_off = (uint32_t)(((lane & 7) + ((lane >> 3) & 1) * 8 + warpM * 32) * 80
                                      + ((lane >> 4) & 1) * 16);
    const uint32_t b_off = (uint32_t)(((lane & 7) + ((lane >> 4) & 1) * 8 + warpN * 64) * 80
                                      + ((lane >> 3) & 1) * 16);

    float acc[2][8][4];
#pragma unroll
    for (int mt = 0; mt < 2; mt++)
#pragma unroll
        for (int nt = 0; nt < 8; nt++)
#pragma unroll
            for (int r = 0; r < 4; r++) acc[mt][nt][r] = 0.f;

    uint4 pa0, pa1;

    // ---- prologue: B(0),B(1) in flight; A(0)->smem buf0; A(1)->regs ----
#pragma unroll
    for (int st = 0; st < 2; st++) {
        const uint32_t bd = b_dst + (uint32_t)st * BSTG_;
        const __half* g0 = Bp + st * 32;
#pragma unroll
        for (int c = 0; c < 2; c++)
            CP_ASYNC16(bd + c * 16u, g0 + c * 8);
        CP_COMMIT();
    }
    pa0 = *(const uint4*)(Ap);
    pa1 = *(const uint4*)(Ap + 8);
    sts_b128(a_sts,       pa0);
    sts_b128(a_sts + 16u, pa1);
    pa0 = *(const uint4*)(Ap + 32);
    pa1 = *(const uint4*)(Ap + 40);

    int bs = 0;
#pragma unroll 1
    for (int s = 0; s < 32; s++) {
        CP_WAIT1();
        __syncthreads();

        if (s < 31) {
            const uint32_t an = a_sts + (uint32_t)((s + 1) & 1) * ASTG_;
            sts_b128(an,       pa0);
            sts_b128(an + 16u, pa1);
        }
        if (s + 2 < 32) {
            const int k0n = (s + 2) << 5;
            pa0 = *(const uint4*)(Ap + k0n);
            pa1 = *(const uint4*)(Ap + k0n + 8);
            const int bs2 = (bs + 2 >= 3) ? bs - 1 : bs + 2;
            const uint32_t bd = b_dst + (uint32_t)bs2 * BSTG_;
#pragma unroll
            for (int c = 0; c < 2; c++)
                CP_ASYNC16(bd + c * 16u, Bp + k0n + c * 8);
        }
        CP_COMMIT();

        const uint32_t ca = sb + (uint32_t)(s & 1) * ASTG_;
        const uint32_t cb = sb + BBASE_ + (uint32_t)bs * BSTG_;
#pragma unroll
        for (int kk = 0; kk < 2; kk++) {
            const uint32_t ko = (uint32_t)kk * 32u;
            uint32_t ah[2][4];
            LDSM4(ah[0], ca + a_off + ko);
            LDSM4(ah[1], ca + a_off + 1280u + ko);
#pragma unroll
            for (int ng = 0; ng < 4; ng++) {
                uint32_t bh4[4];
                LDSM4(bh4, cb + b_off + (uint32_t)ng * 1280u + ko);
                mma16816h(acc[0][2 * ng],     ah[0], bh4);
                mma16816h(acc[0][2 * ng + 1], ah[0], bh4 + 2);
                mma16816h(acc[1][2 * ng],     ah[1], bh4);
                mma16816h(acc[1][2 * ng + 1], ah[1], bh4 + 2);
            }
        }
        bs = (bs + 1 >= 3) ? 0 : bs + 1;
    }

    const int g = lane >> 2, t = lane & 3;
#pragma unroll
    for (int mt = 0; mt < 2; mt++) {
        const int row0 = bm + warpM * 32 + mt * 16 + g;
        const int row1 = row0 + 8;
#pragma unroll
        for (int nt = 0; nt < 8; nt++) {
            const int col = bn + warpN * 64 + nt * 8 + t * 2;
            const float2 bv2 = *(const float2*)(bias + col);
            *(float2*)(C + (size_t)row0 * D_ + col) =
                make_float2(acc[mt][nt][0] + bv2.x, acc[mt][nt][1] + bv2.y);
            *(float2*)(C + (size_t)row1 * D_ + col) =
                make_float2(acc[mt][nt][2] + bv2.x, acc[mt][nt][3] + bv2.y);
        }
    }
}

// ---------------------------------------------------------------------------
// weight fp16 convert (tiny: 3 x 1M elements)
// ---------------------------------------------------------------------------
__global__ void __launch_bounds__(256) cvt_w_kernel(
    const float* __restrict__ w0, const float* __restrict__ w1,
    const float* __restrict__ w2)
{
    const float* src = (blockIdx.y == 0) ? w0 : (blockIdx.y == 1) ? w1 : w2;
    const size_t i4 = (size_t)blockIdx.x * 256 + threadIdx.x;
    float4 v = ((const float4*)src)[i4];
    const size_t o = ((size_t)blockIdx.y << 20) + i4 * 4;
    *(uint2*)(g_Wh + o) = make_uint2(h2_u32(v.x, v.y), h2_u32(v.z, v.w));
}

__global__ void zero_acc_kernel()
{
    const int i = blockIdx.x * 256 + threadIdx.x;
    if (i < B_ * D_) g_qnorm[i] = 0.f;
    if (i < B_ * H_ * DH_ * DH_) g_kv[i] = 0.f;
}

// ---------------------------------------------------------------------------
// fused knorm + kv (fp16 K/V): kv[b,h,d,e] += sum_n knorm(k)[.,d] * v[.,e]
// grid (128 bh, 16 chunks of 256 rows)
// ---------------------------------------------------------------------------
__global__ void __launch_bounds__(256) kv_fused_kernel()
{
    __shared__ __align__(16) float Ks[64][64];
    __shared__ __align__(16) float Vs[64][64];
    const int tid = threadIdx.x;
    const int bh  = blockIdx.x;
    const int b   = bh >> 4, h = bh & 15;
    const int n0  = blockIdx.y << 8;
    const size_t base = (size_t)b * N_ * D_ + (size_t)h * DH_;
    const int d0 = (tid & 15) << 2;
    const int e0 = (tid >> 4) << 2;

    float acc[4][4];
#pragma unroll
    for (int i = 0; i < 4; i++)
#pragma unroll
        for (int j = 0; j < 4; j++) acc[i][j] = 0.f;

    for (int tile = 0; tile < 256; tile += 64) {
        __syncthreads();
#pragma unroll
        for (int it = 0; it < 4; it++) {
            const int rj = (it << 4) + (tid >> 4);
            const int q  = (tid & 15) << 2;
            const size_t gi = base + (size_t)(n0 + tile + rj) * D_ + q;
            const uint2 kraw = *(const uint2*)(g_Kh + gi);
            const uint2 vraw = *(const uint2*)(g_Vh + gi);
            float2 k01 = __half22float2(*(const __half2*)&kraw.x);
            float2 k23 = __half22float2(*(const __half2*)&kraw.y);
            float4 kd = make_float4(k01.x, k01.y, k23.x, k23.y);
            float s = kd.x * kd.x + kd.y * kd.y + kd.z * kd.z + kd.w * kd.w;
            s += __shfl_xor_sync(0xffffffffu, s, 1);
            s += __shfl_xor_sync(0xffffffffu, s, 2);
            s += __shfl_xor_sync(0xffffffffu, s, 4);
            s += __shfl_xor_sync(0xffffffffu, s, 8);
            const float inv = 1.0f / fmaxf(sqrtf(s), 1e-12f);
            kd.x *= inv; kd.y *= inv; kd.z *= inv; kd.w *= inv;
            *(float4*)&Ks[rj][q] = kd;
            float2 v01 = __half22float2(*(const __half2*)&vraw.x);
            float2 v23 = __half22float2(*(const __half2*)&vraw.y);
            *(float4*)&Vs[rj][q] = make_float4(v01.x, v01.y, v23.x, v23.y);
        }
        __syncthreads();
#pragma unroll 8
        for (int j = 0; j < 64; j++) {
            const float4 kd = *(const float4*)&Ks[j][d0];
            const float4 ve = *(const float4*)&Vs[j][e0];
            const float kda[4] = {kd.x, kd.y, kd.z, kd.w};
            const float vea[4] = {ve.x, ve.y, ve.z, ve.w};
#pragma unroll
            for (int di = 0; di < 4; di++)
#pragma unroll
                for (int ei = 0; ei < 4; ei++)
                    acc[di][ei] = fmaf(kda[di], vea[ei], acc[di][ei]);
        }
    }

    float* outp = g_kv + (size_t)bh * (DH_ * DH_);
#pragma unroll
    for (int di = 0; di < 4; di++)
#pragma unroll
        for (int ei = 0; ei < 4; ei++)
            atomicAdd(&outp[(d0 + di) * DH_ + e0 + ei], acc[di][ei]);
}

// ---------------------------------------------------------------------------
// GT_b[j][h*64+d] = (sum_e kv[b,h][d][e] * Wo[j][h*64+e]) / max(sqrt(qn),eps)
// emitted fp16.
// ---------------------------------------------------------------------------
__global__ void __launch_bounds__(256) gt_kernel(const float* __restrict__ Wo)
{
    __shared__ __align__(16) float kvs[64][65];
    __shared__ __align__(16) float Wos[64][65];
    const int tid = threadIdx.x;
    const int jt = blockIdx.x, h = blockIdx.y, b = blockIdx.z;
    const float* kvp = g_kv + (size_t)(b * H_ + h) * (DH_ * DH_);

#pragma unroll
    for (int i = 0; i < 16; i++) {
        const int idx = tid + (i << 8);
        const int r = idx >> 6, e = idx & 63;
        kvs[r][e] = kvp[idx];
        Wos[r][e] = Wo[(size_t)(jt * 64 + r) * D_ + h * 64 + e];
    }
    __syncthreads();

    const int tj = (tid >> 4) << 2;
    const int td = (tid & 15) << 2;
    float acc[4][4];
#pragma unroll
    for (int i = 0; i < 4; i++)
#pragma unroll
        for (int j = 0; j < 4; j++) acc[i][j] = 0.f;

#pragma unroll 16
    for (int e = 0; e < 64; e++) {
        float wv[4], kvv[4];
#pragma unroll
        for (int i = 0; i < 4; i++) { wv[i] = Wos[tj + i][e]; kvv[i] = kvs[td + i][e]; }
#pragma unroll
        for (int i = 0; i < 4; i++)
#pragma unroll
            for (int j = 0; j < 4; j++)
                acc[i][j] = fmaf(wv[i], kvv[j], acc[i][j]);
    }

    float sc[4];
#pragma unroll
    for (int j = 0; j < 4; j++)
        sc[j] = 1.0f / fmaxf(sqrtf(g_qnorm[b * D_ + h * 64 + td + j]), 1e-12f);

    const size_t ob = ((size_t)b << 20) + (size_t)(jt * 64 + tj) * D_ + h * 64 + td;
#pragma unroll
    for (int i = 0; i < 4; i++)
        *(uint2*)(g_GTh + ob + (size_t)i * D_) =
            make_uint2(h2_u32(acc[i][0] * sc[0], acc[i][1] * sc[1]),
                       h2_u32(acc[i][2] * sc[2], acc[i][3] * sc[3]));
}

// ---------------------------------------------------------------------------
extern "C" void kernel_launch(void* const* d_in, const int* in_sizes, int n_in,
                              void* d_out, int out_size)
{
    (void)in_sizes; (void)n_in; (void)out_size;
    const float* query = (const float*)d_in[0];
    const float* key   = (const float*)d_in[1];
    const float* value = (const float*)d_in[2];
    const int*   mask  = (const int*)d_in[3];   // bool materialized as int32
    const float* Wq = (const float*)d_in[4];
    const float* bq = (const float*)d_in[5];
    const float* Wk = (const float*)d_in[6];
    const float* bk = (const float*)d_in[7];
    const float* Wv = (const float*)d_in[8];
    const float* bv = (const float*)d_in[9];
    const float* Wo = (const float*)d_in[10];
    const float* bo = (const float*)d_in[11];
    float* out = (float*)d_out;

    __half *Wh, *Qh, *Kh, *Vh;
    cudaGetSymbolAddress((void**)&Wh, g_Wh);
    cudaGetSymbolAddress((void**)&Qh, g_Qh);
    cudaGetSymbolAddress((void**)&Kh, g_Kh);
    cudaGetSymbolAddress((void**)&Vh, g_Vh);

    cudaFuncSetAttribute(gemm_qkv<0>, cudaFuncAttributeMaxDynamicSharedMemorySize, GEMM_SMEM);
    cudaFuncSetAttribute(gemm_qkv<1>, cudaFuncAttributeMaxDynamicSharedMemorySize, GEMM_SMEM);
    cudaFuncSetAttribute(gemm_qkv<2>, cudaFuncAttributeMaxDynamicSharedMemorySize, GEMM_SMEM);
    cudaFuncSetAttribute(gemm_out,    cudaFuncAttributeMaxDynamicSharedMemorySize, GEMM_SMEM);

    const size_t WN = (size_t)D_ * D_;

    dim3 gblk(256);
    dim3 ggrid(D_ / 128, M_ / 128);      // (8, 256)

    cvt_w_kernel<<<dim3(1024, 3), 256>>>(Wq, Wk, Wv);
    zero_acc_kernel<<<(B_ * H_ * DH_ * DH_ + 255) / 256, 256>>>();

    gemm_qkv<1><<<ggrid, gblk, GEMM_SMEM>>>(query, Wh,          bq, nullptr, Qh);
    gemm_qkv<2><<<ggrid, gblk, GEMM_SMEM>>>(key,   Wh + WN,     bk, mask,    Kh);
    gemm_qkv<0><<<ggrid, gblk, GEMM_SMEM>>>(value, Wh + 2 * WN, bv, nullptr, Vh);

    kv_fused_kernel<<<dim3(B_ * H_, 16), 256>>>();
    gt_kernel<<<dim3(16, 16, 8), 256>>>(Wo);

    gemm_out<<<ggrid, gblk, GEMM_SMEM>>>(Qh, bo, out);
}

// round 16
// speedup vs baseline: 1.0468x; 1.0468x over previous
#include <cuda_runtime.h>
#include <cuda_fp16.h>
#include <math.h>
#include <stdint.h>

#define B_  8
#define N_  4096
#define D_  1024
#define H_  16
#define DH_ 64
#define M_  (B_ * N_)   // 32768 rows

// ---------------- scratch (static device memory; allocation-free) ----------
__device__ __half g_Wh[(size_t)3 * D_ * D_];     // fp16 Wq|Wk|Wv
__device__ float g_Q[(size_t)M_ * D_];           // post-elu Q (fp32)
__device__ __half g_Kh[(size_t)M_ * D_];         // fp16 K (post elu+mask)
__device__ __half g_Vh[(size_t)M_ * D_];         // fp16 V
__device__ __half g_GTh[(size_t)B_ * D_ * D_];   // folded Wo∘kv∘qnorm (fp16)
__device__ float g_qnorm[B_ * D_];
__device__ float g_kv[B_ * H_ * DH_ * DH_];

// =====================  helpers  ===========================================
__device__ __forceinline__ uint32_t smem_addr_u32(const void* p) {
    uint32_t a;
    asm("{ .reg .u64 t; cvta.to.shared.u64 t, %1; cvt.u32.u64 %0, t; }"
        : "=r"(a) : "l"(p));
    return a;
}

__device__ __forceinline__ uint32_t h2_u32(float x, float y) {
    __half2 h = __floats2half2_rn(x, y);
    return *reinterpret_cast<uint32_t*>(&h);
}

__device__ __forceinline__ void sts_b64(uint32_t a, uint32_t x, uint32_t y) {
    asm volatile("st.shared.v2.b32 [%0], {%1, %2};" :: "r"(a), "r"(x), "r"(y) : "memory");
}

__device__ __forceinline__ void sts_b128(uint32_t a, uint4 v) {
    asm volatile("st.shared.v4.b32 [%0], {%1, %2, %3, %4};"
                 :: "r"(a), "r"(v.x), "r"(v.y), "r"(v.z), "r"(v.w) : "memory");
}

// fp16 MMA, fp32 accumulate
__device__ __forceinline__ void mma16816h(float* c, const uint32_t* a, const uint32_t* b) {
    asm volatile(
        "mma.sync.aligned.m16n8k16.row.col.f32.f16.f16.f32 "
        "{%0,%1,%2,%3}, {%4,%5,%6,%7}, {%8,%9}, {%0,%1,%2,%3};"
        : "+f"(c[0]), "+f"(c[1]), "+f"(c[2]), "+f"(c[3])
        : "r"(a[0]), "r"(a[1]), "r"(a[2]), "r"(a[3]), "r"(b[0]), "r"(b[1]));
}

#define LDSM4(r, a)                                                            \
    asm volatile("ldmatrix.sync.aligned.m8n8.x4.shared.b16 {%0,%1,%2,%3}, [%4];" \
        : "=r"((r)[0]), "=r"((r)[1]), "=r"((r)[2]), "=r"((r)[3]) : "r"(a))

#define LDSM4T(r, a)                                                           \
    asm volatile("ldmatrix.sync.aligned.m8n8.x4.trans.shared.b16 {%0,%1,%2,%3}, [%4];" \
        : "=r"((r)[0]), "=r"((r)[1]), "=r"((r)[2]), "=r"((r)[3]) : "r"(a))

#define CP_ASYNC16(dst, src)                                                   \
    asm volatile("cp.async.cg.shared.global [%0], [%1], 16;"                   \
        :: "r"(dst), "l"(src) : "memory")
#define CP_COMMIT()  asm volatile("cp.async.commit_group;" ::: "memory")
#define CP_WAIT1()   asm volatile("cp.async.wait_group 1;" ::: "memory")

// ---------------------------------------------------------------------------
// GEMM smem: A 2-stage (10240 B each: 128 rows x 80B); B 3-stage at +20480.
// ---------------------------------------------------------------------------
#define ASTG_ 10240u
#define BBASE_ 20480u
#define BSTG_ 10240u
static constexpr size_t GEMM_SMEM = 2 * 10240 + 3 * 10240;   // 51200 B

// ---------------------------------------------------------------------------
// fp16 HMMA mainloop (fp32 A in global): acc += A @ Bh^T over K=1024.
// ---------------------------------------------------------------------------
__device__ __forceinline__ void gemm_mainloop(
    const float* Ap, const __half* Bp,
    uint32_t sb, uint32_t a_sts, uint32_t b_dst,
    uint32_t a_off, uint32_t b_off, float acc[2][8][4])
{
    float4 pa[4];

#pragma unroll
    for (int st = 0; st < 2; st++) {
        const uint32_t bd = b_dst + (uint32_t)st * BSTG_;
        const __half* g0 = Bp + st * 32;
#pragma unroll
        for (int c = 0; c < 2; c++)
            CP_ASYNC16(bd + c * 16u, g0 + c * 8);
        CP_COMMIT();
    }
#pragma unroll
    for (int i = 0; i < 4; i++)
        pa[i] = *(const float4*)(Ap + (size_t)(i << 5) * D_);
#pragma unroll
    for (int i = 0; i < 4; i++)
        sts_b64(a_sts + (uint32_t)(i * 32 * 80),
                h2_u32(pa[i].x, pa[i].y), h2_u32(pa[i].z, pa[i].w));
#pragma unroll
    for (int i = 0; i < 4; i++)
        pa[i] = *(const float4*)(Ap + 32 + (size_t)(i << 5) * D_);

    int bs = 0;
#pragma unroll 1
    for (int s = 0; s < 32; s++) {
        CP_WAIT1();
        __syncthreads();

        if (s < 31) {
            const uint32_t an = a_sts + (uint32_t)((s + 1) & 1) * ASTG_;
#pragma unroll
            for (int i = 0; i < 4; i++)
                sts_b64(an + (uint32_t)(i * 32 * 80),
                        h2_u32(pa[i].x, pa[i].y), h2_u32(pa[i].z, pa[i].w));
        }
        if (s + 2 < 32) {
            const int k0n = (s + 2) << 5;
#pragma unroll
            for (int i = 0; i < 4; i++)
                pa[i] = *(const float4*)(Ap + k0n + (size_t)(i << 5) * D_);
            const int bs2 = (bs + 2 >= 3) ? bs - 1 : bs + 2;
            const uint32_t bd = b_dst + (uint32_t)bs2 * BSTG_;
#pragma unroll
            for (int c = 0; c < 2; c++)
                CP_ASYNC16(bd + c * 16u, Bp + k0n + c * 8);
        }
        CP_COMMIT();

        const uint32_t ca = sb + (uint32_t)(s & 1) * ASTG_;
        const uint32_t cb = sb + BBASE_ + (uint32_t)bs * BSTG_;
#pragma unroll
        for (int kk = 0; kk < 2; kk++) {
            const uint32_t ko = (uint32_t)kk * 32u;
            uint32_t ah[2][4];
            LDSM4(ah[0], ca + a_off + ko);
            LDSM4(ah[1], ca + a_off + 1280u + ko);
#pragma unroll
            for (int ng = 0; ng < 4; ng++) {
                uint32_t bh4[4];
                LDSM4(bh4, cb + b_off + (uint32_t)ng * 1280u + ko);
                mma16816h(acc[0][2 * ng],     ah[0], bh4);
                mma16816h(acc[0][2 * ng + 1], ah[0], bh4 + 2);
                mma16816h(acc[1][2 * ng],     ah[1], bh4);
                mma16816h(acc[1][2 * ng + 1], ah[1], bh4 + 2);
            }
        }
        bs = (bs + 1 >= 3) ? 0 : bs + 1;
    }
}

// ---------------------------------------------------------------------------
// HMMA GEMM wrapper (R14 config).
//   MODE 0: plain, fp16 out (V)
//   MODE 1: 1+elu + fused qnorm atomics, fp32 out (Q)
//   MODE 2: 1+elu + mask, fp16 out (K)
//   MODE 3: plain, per-batch B, fp32 out (final output)
// ---------------------------------------------------------------------------
template <int MODE>
__global__ void __launch_bounds__(256, 2)
gemm_fp16(const float* __restrict__ A, const __half* __restrict__ Bh,
          const float* __restrict__ bias, const int* __restrict__ mask,
          float* __restrict__ Cf, __half* __restrict__ Ch)
{
    extern __shared__ __align__(16) char smem[];
    const uint32_t sb = smem_addr_u32(smem);
    const int tid  = threadIdx.x;
    const int lane = tid & 31;
    const int wid  = tid >> 5;
    const int warpM = wid & 3;
    const int warpN = wid >> 2;
    const int bm = blockIdx.y << 7;
    const int bn = blockIdx.x << 7;

    if (MODE == 3) Bh += ((size_t)(bm >> 12)) << 20;

    const int r0 = tid >> 3;
    const int c4 = tid & 7;
    const float* Ap = A + (size_t)(bm + r0) * D_ + (c4 << 2);
    const uint32_t a_sts = sb + (uint32_t)(r0 * 80 + c4 * 8);

    const int brow = tid >> 1;
    const int bpart = tid & 1;
    const __half* Bp = Bh + (size_t)(bn + brow) * D_ + bpart * 16;
    const uint32_t b_dst = sb + BBASE_ + (uint32_t)(brow * 80 + bpart * 32);

    const uint32_t a_off = (uint32_t)(((lane & 7) + ((lane >> 3) & 1) * 8 + warpM * 32) * 80
                                      + ((lane >> 4) & 1) * 16);
    const uint32_t b_off = (uint32_t)(((lane & 7) + ((lane >> 4) & 1) * 8 + warpN * 64) * 80
                                      + ((lane >> 3) & 1) * 16);

    float acc[2][8][4];
#pragma unroll
    for (int mt = 0; mt < 2; mt++)
#pragma unroll
        for (int nt = 0; nt < 8; nt++)
#pragma unroll
            for (int r = 0; r < 4; r++) acc[mt][nt][r] = 0.f;

    gemm_mainloop(Ap, Bp, sb, a_sts, b_dst, a_off, b_off, acc);

    // ---- epilogue ----
    const int g = lane >> 2, t = lane & 3;
    float cs[8][2];
    if (MODE == 1) {
#pragma unroll
        for (int nt = 0; nt < 8; nt++) { cs[nt][0] = 0.f; cs[nt][1] = 0.f; }
    }

#pragma unroll
    for (int mt = 0; mt < 2; mt++) {
        const int row0 = bm + warpM * 32 + mt * 16 + g;
        const int row1 = row0 + 8;
        int m0 = 0, m1 = 0;
        if (MODE == 2) { m0 = mask[row0]; m1 = mask[row1]; }
#pragma unroll
        for (int nt = 0; nt < 8; nt++) {
            const int col = bn + warpN * 64 + nt * 8 + t * 2;
            const float2 bv2 = *(const float2*)(bias + col);
            float v0 = acc[mt][nt][0] + bv2.x;
            float v1 = acc[mt][nt][1] + bv2.y;
            float v2 = acc[mt][nt][2] + bv2.x;
            float v3 = acc[mt][nt][3] + bv2.y;
            if (MODE == 1 || MODE == 2) {
                v0 = (v0 > 0.f) ? (v0 + 1.f) : expf(v0);
                v1 = (v1 > 0.f) ? (v1 + 1.f) : expf(v1);
                v2 = (v2 > 0.f) ? (v2 + 1.f) : expf(v2);
                v3 = (v3 > 0.f) ? (v3 + 1.f) : expf(v3);
            }
            if (MODE == 2) {
                if (m0) { v0 = 0.f; v1 = 0.f; }
                if (m1) { v2 = 0.f; v3 = 0.f; }
            }
            if (MODE == 1) {
                cs[nt][0] += v0 * v0 + v2 * v2;
                cs[nt][1] += v1 * v1 + v3 * v3;
            }
            if (MODE == 0 || MODE == 2) {
                *(uint32_t*)(Ch + (size_t)row0 * D_ + col) = h2_u32(v0, v1);
                *(uint32_t*)(Ch + (size_t)row1 * D_ + col) = h2_u32(v2, v3);
            } else {
                *(float2*)(Cf + (size_t)row0 * D_ + col) = make_float2(v0, v1);
                *(float2*)(Cf + (size_t)row1 * D_ + col) = make_float2(v2, v3);
            }
        }
    }

    if (MODE == 1) {
        const int b = bm >> 12;
#pragma unroll
        for (int nt = 0; nt < 8; nt++) {
#pragma unroll
            for (int c = 0; c < 2; c++) {
                float s = cs[nt][c];
                s += __shfl_xor_sync(0xffffffffu, s, 4);
                s += __shfl_xor_sync(0xffffffffu, s, 8);
                s += __shfl_xor_sync(0xffffffffu, s, 16);
                if (g == 0) {
                    const int col = bn + warpN * 64 + nt * 8 + t * 2 + c;
                    atomicAdd(&g_qnorm[b * D_ + col], s);
                }
            }
        }
    }
}

// ---------------------------------------------------------------------------
// weight fp16 convert (tiny: 3 x 1M elements)
// ---------------------------------------------------------------------------
__global__ void __launch_bounds__(256) cvt_w_kernel(
    const float* __restrict__ w0, const float* __restrict__ w1,
    const float* __restrict__ w2)
{
    const float* src = (blockIdx.y == 0) ? w0 : (blockIdx.y == 1) ? w1 : w2;
    const size_t i4 = (size_t)blockIdx.x * 256 + threadIdx.x;
    float4 v = ((const float4*)src)[i4];
    const size_t o = ((size_t)blockIdx.y << 20) + i4 * 4;
    *(uint2*)(g_Wh + o) = make_uint2(h2_u32(v.x, v.y), h2_u32(v.z, v.w));
}

__global__ void zero_qnorm_kernel()
{
    const int i = blockIdx.x * 256 + threadIdx.x;
    if (i < B_ * D_) g_qnorm[i] = 0.f;
}

// ---------------------------------------------------------------------------
// HMMA kv kernel: kv_h[d][e] = sum_n knorm(k)[n][d] * v[n][e]  (per b,h)
// 128 blocks (one per bh), 128 threads / 4 warps; warp owns a 32x32 output
// quadrant over the full K=4096 -> plain store, no atomics.
// Both operands loaded with ldmatrix.x4.trans from [n][feat] smem tiles.
// K rows L2-normalized in registers on the LDG path (8 lanes/row shuffle).
// smem rows: 72 halfs = 144B (bank-conflict-free for ldmatrix).
// ---------------------------------------------------------------------------
__global__ void __launch_bounds__(128, 1) kv_hmma_kernel()
{
    __shared__ __align__(16) __half KT[2][64][72];
    __shared__ __align__(16) __half VT[3][64][72];

    const int tid  = threadIdx.x;
    const int lane = tid & 31;
    const int wid  = tid >> 5;
    const int wm   = wid & 1;        // d-half
    const int wn   = wid >> 1;       // e-half
    const int bh   = blockIdx.x;
    const int b    = bh >> 4, h = bh & 15;
    const size_t base = ((size_t)b * N_) * D_ + (size_t)h * DH_;

    const uint32_t k0a = smem_addr_u32(&KT[0][0][0]);
    const uint32_t v0a = smem_addr_u32(&VT[0][0][0]);

    // K load/norm mapping: 8 threads per row; rows (tid>>3)+16i, seg tid&7
    const int krow = tid >> 3;
    const int kseg = tid & 7;
    // V cp.async mapping: 2 threads per row, 4x16B chunks each
    const int vrow = tid >> 1;
    const int vp   = tid & 1;

    // ldmatrix.trans offsets (derived from PTX fragment layouts):
    // A (= K^T): tile order (d0,n0),(d0+16B? no: d+16B),(n+8,d0),(n+8,d+16B)
    const uint32_t a_toff = (uint32_t)(((lane & 7) + ((lane >> 4) & 1) * 8) * 144
                                       + wm * 64 + ((lane >> 3) & 1) * 16);
    // B (= V^T): lanes bit3 -> k-row+8, bit4 -> e-col+16B
    const uint32_t b_toff = (uint32_t)(((lane & 7) + ((lane >> 3) & 1) * 8) * 144
                                       + wn * 64 + ((lane >> 4) & 1) * 16);

    float acc[2][4][4];
#pragma unroll
    for (int mi = 0; mi < 2; mi++)
#pragma unroll
        for (int ni = 0; ni < 4; ni++)
#pragma unroll
            for (int r = 0; r < 4; r++) acc[mi][ni][r] = 0.f;

    uint4 kr[4];

    // ---- prologue ----
    // V(0), V(1) in flight
#pragma unroll
    for (int st = 0; st < 2; st++) {
        const uint32_t vd = v0a + (uint32_t)st * 9216u
                          + (uint32_t)(vrow * 144 + vp * 64);
        const __half* gv = g_Vh + base + (size_t)(st * 64 + vrow) * D_ + vp * 32;
#pragma unroll
        for (int c = 0; c < 4; c++)
            CP_ASYNC16(vd + c * 16u, gv + c * 8);
        CP_COMMIT();
    }
    // K(0): LDG -> norm -> STS buf0
#pragma unroll
    for (int i = 0; i < 4; i++)
        kr[i] = *(const uint4*)(g_Kh + base + (size_t)(krow + 16 * i) * D_ + kseg * 8);
#pragma unroll
    for (int i = 0; i < 4; i++) {
        float f[8];
        const __half2* hp = (const __half2*)&kr[i];
#pragma unroll
        for (int j = 0; j < 4; j++) {
            float2 fp = __half22float2(hp[j]);
            f[2 * j] = fp.x; f[2 * j + 1] = fp.y;
        }
        float s = 0.f;
#pragma unroll
        for (int j = 0; j < 8; j++) s += f[j] * f[j];
        s += __shfl_xor_sync(0xffffffffu, s, 1);
        s += __shfl_xor_sync(0xffffffffu, s, 2);
        s += __shfl_xor_sync(0xffffffffu, s, 4);
        const float inv = 1.0f / fmaxf(sqrtf(s), 1e-12f);
        uint4 packed;
        packed.x = h2_u32(f[0] * inv, f[1] * inv);
        packed.y = h2_u32(f[2] * inv, f[3] * inv);
        packed.z = h2_u32(f[4] * inv, f[5] * inv);
        packed.w = h2_u32(f[6] * inv, f[7] * inv);
        sts_b128(k0a + (uint32_t)((krow + 16 * i) * 144 + kseg * 16), packed);
    }
    // K(1): LDG -> regs
#pragma unroll
    for (int i = 0; i < 4; i++)
        kr[i] = *(const uint4*)(g_Kh + base + (size_t)(64 + krow + 16 * i) * D_ + kseg * 8);

    int vs = 0;   // t % 3
#pragma unroll 1
    for (int t = 0; t < 64; t++) {
        CP_WAIT1();
        __syncthreads();

        // process K(t+1) regs -> buf (t+1)&1
        if (t < 63) {
            const uint32_t kb = k0a + (uint32_t)((t + 1) & 1) * 9216u;
#pragma unroll
            for (int i = 0; i < 4; i++) {
                float f[8];
                const __half2* hp = (const __half2*)&kr[i];
#pragma unroll
                for (int j = 0; j < 4; j++) {
                    float2 fp = __half22float2(hp[j]);
                    f[2 * j] = fp.x; f[2 * j + 1] = fp.y;
                }
                float s = 0.f;
#pragma unroll
                for (int j = 0; j < 8; j++) s += f[j] * f[j];
                s += __shfl_xor_sync(0xffffffffu, s, 1);
                s += __shfl_xor_sync(0xffffffffu, s, 2);
                s += __shfl_xor_sync(0xffffffffu, s, 4);
                const float inv = 1.0f / fmaxf(sqrtf(s), 1e-12f);
                uint4 packed;
                packed.x = h2_u32(f[0] * inv, f[1] * inv);
                packed.y = h2_u32(f[2] * inv, f[3] * inv);
                packed.z = h2_u32(f[4] * inv, f[5] * inv);
                packed.w = h2_u32(f[6] * inv, f[7] * inv);
                sts_b128(kb + (uint32_t)((krow + 16 * i) * 144 + kseg * 16), packed);
            }
        }
        // prefetch K(t+2), issue V(t+2)
        if (t + 2 < 64) {
            const int n2 = (t + 2) * 64;
#pragma unroll
            for (int i = 0; i < 4; i++)
                kr[i] = *(const uint4*)(g_Kh + base + (size_t)(n2 + krow + 16 * i) * D_ + kseg * 8);
            const int vs2 = (vs + 2 >= 3) ? vs - 1 : vs + 2;
            const uint32_t vd = v0a + (uint32_t)vs2 * 9216u
                              + (uint32_t)(vrow * 144 + vp * 64);
            const __half* gv = g_Vh + base + (size_t)(n2 + vrow) * D_ + vp * 32;
#pragma unroll
            for (int c = 0; c < 4; c++)
                CP_ASYNC16(vd + c * 16u, gv + c * 8);
        }
        CP_COMMIT();

        // ---- compute tile t ----
        const uint32_t ka = k0a + (uint32_t)(t & 1) * 9216u;
        const uint32_t va = v0a + (uint32_t)vs * 9216u;
#pragma unroll
        for (int k16 = 0; k16 < 4; k16++) {
            const uint32_t nb = (uint32_t)(k16 * 16 * 144);
            uint32_t a0[4], a1[4], bv0[4], bv1[4];
            LDSM4T(a0, ka + a_toff + nb);          // d: wm*32 .. +15
            LDSM4T(a1, ka + a_toff + nb + 32u);    // d: wm*32+16 .. +31
            LDSM4T(bv0, va + b_toff + nb);         // e: wn*32 .. +15
            LDSM4T(bv1, va + b_toff + nb + 32u);   // e: wn*32+16 .. +31
            mma16816h(acc[0][0], a0, bv0);
            mma16816h(acc[0][1], a0, bv0 + 2);
            mma16816h(acc[0][2], a0, bv1);
            mma16816h(acc[0][3], a0, bv1 + 2);
            mma16816h(acc[1][0], a1, bv0);
            mma16816h(acc[1][1], a1, bv0 + 2);
            mma16816h(acc[1][2], a1, bv1);
            mma16816h(acc[1][3], a1, bv1 + 2);
        }
        vs = (vs + 1 >= 3) ? 0 : vs + 1;
    }

    // ---- store: plain fp32, no atomics ----
    const int g = lane >> 2, tq = lane & 3;
    float* outp = g_kv + (size_t)bh * (DH_ * DH_);
#pragma unroll
    for (int mi = 0; mi < 2; mi++) {
        const int d0 = wm * 32 + mi * 16 + g;
#pragma unroll
        for (int ni = 0; ni < 4; ni++) {
            const int e = wn * 32 + ni * 8 + tq * 2;
            *(float2*)(outp + (d0)     * DH_ + e) = make_float2(acc[mi][ni][0], acc[mi][ni][1]);
            *(float2*)(outp + (d0 + 8) * DH_ + e) = make_float2(acc[mi][ni][2], acc[mi][ni][3]);
        }
    }
}

// ---------------------------------------------------------------------------
// GT_b[j][h*64+d] = (sum_e kv[b,h][d][e] * Wo[j][h*64+e]) / max(sqrt(qn),eps)
// emitted fp16.
// ---------------------------------------------------------------------------
__global__ void __launch_bounds__(256) gt_kernel(const float* __restrict__ Wo)
{
    __shared__ __align__(16) float kvs[64][65];
    __shared__ __align__(16) float Wos[64][65];
    const int tid = threadIdx.x;
    const int jt = blockIdx.x, h = blockIdx.y, b = blockIdx.z;
    const float* kvp = g_kv + (size_t)(b * H_ + h) * (DH_ * DH_);

#pragma unroll
    for (int i = 0; i < 16; i++) {
        const int idx = tid + (i << 8);
        const int r = idx >> 6, e = idx & 63;
        kvs[r][e] = kvp[idx];
        Wos[r][e] = Wo[(size_t)(jt * 64 + r) * D_ + h * 64 + e];
    }
    __syncthreads();

    const int tj = (tid >> 4) << 2;
    const int td = (tid & 15) << 2;
    float acc[4][4];
#pragma unroll
    for (int i = 0; i < 4; i++)
#pragma unroll
        for (int j = 0; j < 4; j++) acc[i][j] = 0.f;

#pragma unroll 16
    for (int e = 0; e < 64; e++) {
        float wv[4], kvv[4];
#pragma unroll
        for (int i = 0; i < 4; i++) { wv[i] = Wos[tj + i][e]; kvv[i] = kvs[td + i][e]; }
#pragma unroll
        for (int i = 0; i < 4; i++)
#pragma unroll
            for (int j = 0; j < 4; j++)
                acc[i][j] = fmaf(wv[i], kvv[j], acc[i][j]);
    }

    float sc[4];
#pragma unroll
    for (int j = 0; j < 4; j++)
        sc[j] = 1.0f / fmaxf(sqrtf(g_qnorm[b * D_ + h * 64 + td + j]), 1e-12f);

    const size_t ob = ((size_t)b << 20) + (size_t)(jt * 64 + tj) * D_ + h * 64 + td;
#pragma unroll
    for (int i = 0; i < 4; i++)
        *(uint2*)(g_GTh + ob + (size_t)i * D_) =
            make_uint2(h2_u32(acc[i][0] * sc[0], acc[i][1] * sc[1]),
                       h2_u32(acc[i][2] * sc[2], acc[i][3] * sc[3]));
}

// ---------------------------------------------------------------------------
extern "C" void kernel_launch(void* const* d_in, const int* in_sizes, int n_in,
                              void* d_out, int out_size)
{
    (void)in_sizes; (void)n_in; (void)out_size;
    const float* query = (const float*)d_in[0];
    const float* key   = (const float*)d_in[1];
    const float* value = (const float*)d_in[2];
    const int*   mask  = (const int*)d_in[3];   // bool materialized as int32
    const float* Wq = (const float*)d_in[4];
    const float* bq = (const float*)d_in[5];
    const float* Wk = (const float*)d_in[6];
    const float* bk = (const float*)d_in[7];
    const float* Wv = (const float*)d_in[8];
    const float* bv = (const float*)d_in[9];
    const float* Wo = (const float*)d_in[10];
    const float* bo = (const float*)d_in[11];
    float* out = (float*)d_out;

    __half *Wh, *GTh, *Kh, *Vh;
    float *Q;
    cudaGetSymbolAddress((void**)&Wh,  g_Wh);
    cudaGetSymbolAddress((void**)&GTh, g_GTh);
    cudaGetSymbolAddress((void**)&Kh,  g_Kh);
    cudaGetSymbolAddress((void**)&Vh,  g_Vh);
    cudaGetSymbolAddress((void**)&Q,   g_Q);

    cudaFuncSetAttribute(gemm_fp16<0>, cudaFuncAttributeMaxDynamicSharedMemorySize, GEMM_SMEM);
    cudaFuncSetAttribute(gemm_fp16<1>, cudaFuncAttributeMaxDynamicSharedMemorySize, GEMM_SMEM);
    cudaFuncSetAttribute(gemm_fp16<2>, cudaFuncAttributeMaxDynamicSharedMemorySize, GEMM_SMEM);
    cudaFuncSetAttribute(gemm_fp16<3>, cudaFuncAttributeMaxDynamicSharedMemorySize, GEMM_SMEM);

    const size_t WN = (size_t)D_ * D_;

    dim3 gblk(256);
    dim3 ggrid(D_ / 128, M_ / 128);      // (8, 256)

    cvt_w_kernel<<<dim3(1024, 3), 256>>>(Wq, Wk, Wv);
    zero_qnorm_kernel<<<(B_ * D_ + 255) / 256, 256>>>();

    gemm_fp16<1><<<ggrid, gblk, GEMM_SMEM>>>(query, Wh,          bq, nullptr, Q,       nullptr);
    gemm_fp16<2><<<ggrid, gblk, GEMM_SMEM>>>(key,   Wh + WN,     bk, mask,    nullptr, Kh);
    gemm_fp16<0><<<ggrid, gblk, GEMM_SMEM>>>(value, Wh + 2 * WN, bv, nullptr, nullptr, Vh);

    kv_hmma_kernel<<<B_ * H_, 128>>>();
    gt_kernel<<<dim3(16, 16, 8), 256>>>(Wo);

    gemm_fp16<3><<<ggrid, gblk, GEMM_SMEM>>>(Q, GTh, bo, nullptr, out, nullptr);
}

// round 17
// speedup vs baseline: 1.0931x; 1.0442x over previous
#include <cuda_runtime.h>
#include <cuda_fp16.h>
#include <math.h>
#include <stdint.h>

#define B_  8
#define N_  4096
#define D_  1024
#define H_  16
#define DH_ 64
#define M_  (B_ * N_)   // 32768 rows

// ---------------- scratch (static device memory; allocation-free) ----------
__device__ __half g_Wh[(size_t)3 * D_ * D_];     // fp16 Wq|Wk|Wv
__device__ float g_Q[(size_t)M_ * D_];           // post-elu Q (fp32)
__device__ __half g_Kh[(size_t)M_ * D_];         // fp16 K (post elu+mask)
__device__ __half g_Vh[(size_t)M_ * D_];         // fp16 V
__device__ __half g_GTh[(size_t)B_ * D_ * D_];   // folded Wo∘kv∘qnorm (fp16)
__device__ float g_qnorm[B_ * D_];
__device__ float g_kv[B_ * H_ * DH_ * DH_];

// =====================  helpers  ===========================================
__device__ __forceinline__ uint32_t smem_addr_u32(const void* p) {
    uint32_t a;
    asm("{ .reg .u64 t; cvta.to.shared.u64 t, %1; cvt.u32.u64 %0, t; }"
        : "=r"(a) : "l"(p));
    return a;
}

__device__ __forceinline__ uint32_t h2_u32(float x, float y) {
    __half2 h = __floats2half2_rn(x, y);
    return *reinterpret_cast<uint32_t*>(&h);
}

__device__ __forceinline__ void sts_b64(uint32_t a, uint32_t x, uint32_t y) {
    asm volatile("st.shared.v2.b32 [%0], {%1, %2};" :: "r"(a), "r"(x), "r"(y) : "memory");
}

__device__ __forceinline__ void sts_b128(uint32_t a, uint4 v) {
    asm volatile("st.shared.v4.b32 [%0], {%1, %2, %3, %4};"
                 :: "r"(a), "r"(v.x), "r"(v.y), "r"(v.z), "r"(v.w) : "memory");
}

// fp16 MMA, fp32 accumulate
__device__ __forceinline__ void mma16816h(float* c, const uint32_t* a, const uint32_t* b) {
    asm volatile(
        "mma.sync.aligned.m16n8k16.row.col.f32.f16.f16.f32 "
        "{%0,%1,%2,%3}, {%4,%5,%6,%7}, {%8,%9}, {%0,%1,%2,%3};"
        : "+f"(c[0]), "+f"(c[1]), "+f"(c[2]), "+f"(c[3])
        : "r"(a[0]), "r"(a[1]), "r"(a[2]), "r"(a[3]), "r"(b[0]), "r"(b[1]));
}

#define LDSM4(r, a)                                                            \
    asm volatile("ldmatrix.sync.aligned.m8n8.x4.shared.b16 {%0,%1,%2,%3}, [%4];" \
        : "=r"((r)[0]), "=r"((r)[1]), "=r"((r)[2]), "=r"((r)[3]) : "r"(a))

#define LDSM4T(r, a)                                                           \
    asm volatile("ldmatrix.sync.aligned.m8n8.x4.trans.shared.b16 {%0,%1,%2,%3}, [%4];" \
        : "=r"((r)[0]), "=r"((r)[1]), "=r"((r)[2]), "=r"((r)[3]) : "r"(a))

#define CP_ASYNC16(dst, src)                                                   \
    asm volatile("cp.async.cg.shared.global [%0], [%1], 16;"                   \
        :: "r"(dst), "l"(src) : "memory")
#define CP_COMMIT()  asm volatile("cp.async.commit_group;" ::: "memory")
#define CP_WAIT1()   asm volatile("cp.async.wait_group 1;" ::: "memory")
#define CP_WAIT2()   asm volatile("cp.async.wait_group 2;" ::: "memory")

// ---------------------------------------------------------------------------
// GEMM smem: A 2-stage (10240 B each: 128 rows x 80B); B 4-stage at +20480.
// ---------------------------------------------------------------------------
#define ASTG_ 10240u
#define BBASE_ 20480u
#define BSTG_ 10240u
static constexpr size_t GEMM_SMEM = 2 * 10240 + 4 * 10240;   // 61440 B

// ---------------------------------------------------------------------------
// fp16 HMMA mainloop (fp32 A in global): acc += A @ Bh^T over K=1024.
// A: LDG fp32 prefetch -> cvt fp16 -> STS (2-stage). B: cp.async fp16
// (4-stage, wait_group 2). One __syncthreads per stage. 32 MMA/warp/stage.
// ---------------------------------------------------------------------------
__device__ __forceinline__ void gemm_mainloop(
    const float* Ap, const __half* Bp,
    uint32_t sb, uint32_t a_sts, uint32_t b_dst,
    uint32_t a_off, uint32_t b_off, float acc[2][8][4])
{
    float4 pa[4];

    // prologue: B(0..2) in flight (3 groups)
#pragma unroll
    for (int st = 0; st < 3; st++) {
        const uint32_t bd = b_dst + (uint32_t)st * BSTG_;
        const __half* g0 = Bp + st * 32;
#pragma unroll
        for (int c = 0; c < 2; c++)
            CP_ASYNC16(bd + c * 16u, g0 + c * 8);
        CP_COMMIT();
    }
#pragma unroll
    for (int i = 0; i < 4; i++)
        pa[i] = *(const float4*)(Ap + (size_t)(i << 5) * D_);
#pragma unroll
    for (int i = 0; i < 4; i++)
        sts_b64(a_sts + (uint32_t)(i * 32 * 80),
                h2_u32(pa[i].x, pa[i].y), h2_u32(pa[i].z, pa[i].w));
#pragma unroll
    for (int i = 0; i < 4; i++)
        pa[i] = *(const float4*)(Ap + 32 + (size_t)(i << 5) * D_);

#pragma unroll 1
    for (int s = 0; s < 32; s++) {
        CP_WAIT2();            // B(s) complete; up to 2 newer groups in flight
        __syncthreads();

        if (s < 31) {
            const uint32_t an = a_sts + (uint32_t)((s + 1) & 1) * ASTG_;
#pragma unroll
            for (int i = 0; i < 4; i++)
                sts_b64(an + (uint32_t)(i * 32 * 80),
                        h2_u32(pa[i].x, pa[i].y), h2_u32(pa[i].z, pa[i].w));
        }
        if (s + 2 < 32) {
            const int k0n = (s + 2) << 5;
#pragma unroll
            for (int i = 0; i < 4; i++)
                pa[i] = *(const float4*)(Ap + k0n + (size_t)(i << 5) * D_);
        }
        if (s + 3 < 32) {      // issue B(s+3) into buffer (s+3)&3
            const int k0n = (s + 3) << 5;
            const uint32_t bd = b_dst + (uint32_t)((s + 3) & 3) * BSTG_;
#pragma unroll
            for (int c = 0; c < 2; c++)
                CP_ASYNC16(bd + c * 16u, Bp + k0n + c * 8);
        }
        CP_COMMIT();

        const uint32_t ca = sb + (uint32_t)(s & 1) * ASTG_;
        const uint32_t cb = sb + BBASE_ + (uint32_t)(s & 3) * BSTG_;
#pragma unroll
        for (int kk = 0; kk < 2; kk++) {
            const uint32_t ko = (uint32_t)kk * 32u;
            uint32_t ah[2][4];
            LDSM4(ah[0], ca + a_off + ko);
            LDSM4(ah[1], ca + a_off + 1280u + ko);
#pragma unroll
            for (int ng = 0; ng < 4; ng++) {
                uint32_t bh4[4];
                LDSM4(bh4, cb + b_off + (uint32_t)ng * 1280u + ko);
                mma16816h(acc[0][2 * ng],     ah[0], bh4);
                mma16816h(acc[0][2 * ng + 1], ah[0], bh4 + 2);
                mma16816h(acc[1][2 * ng],     ah[1], bh4);
                mma16816h(acc[1][2 * ng + 1], ah[1], bh4 + 2);
            }
        }
    }
}

// ---------------------------------------------------------------------------
// HMMA GEMM wrapper.
//   MODE 0: plain, fp16 out (V)
//   MODE 1: 1+elu + fused qnorm atomics, fp32 out (Q)
//   MODE 2: 1+elu + mask, fp16 out (K)
//   MODE 3: plain, per-batch B, fp32 out (final output)
// ---------------------------------------------------------------------------
template <int MODE>
__global__ void __launch_bounds__(256, 2)
gemm_fp16(const float* __restrict__ A, const __half* __restrict__ Bh,
          const float* __restrict__ bias, const int* __restrict__ mask,
          float* __restrict__ Cf, __half* __restrict__ Ch)
{
    extern __shared__ __align__(16) char smem[];
    const uint32_t sb = smem_addr_u32(smem);
    const int tid  = threadIdx.x;
    const int lane = tid & 31;
    const int wid  = tid >> 5;
    const int warpM = wid & 3;
    const int warpN = wid >> 2;
    const int bm = blockIdx.y << 7;
    const int bn = blockIdx.x << 7;

    if (MODE == 3) Bh += ((size_t)(bm >> 12)) << 20;

    const int r0 = tid >> 3;
    const int c4 = tid & 7;
    const float* Ap = A + (size_t)(bm + r0) * D_ + (c4 << 2);
    const uint32_t a_sts = sb + (uint32_t)(r0 * 80 + c4 * 8);

    const int brow = tid >> 1;
    const int bpart = tid & 1;
    const __half* Bp = Bh + (size_t)(bn + brow) * D_ + bpart * 16;
    const uint32_t b_dst = sb + BBASE_ + (uint32_t)(brow * 80 + bpart * 32);

    const uint32_t a_off = (uint32_t)(((lane & 7) + ((lane >> 3) & 1) * 8 + warpM * 32) * 80
                                      + ((lane >> 4) & 1) * 16);
    const uint32_t b_off = (uint32_t)(((lane & 7) + ((lane >> 4) & 1) * 8 + warpN * 64) * 80
                                      + ((lane >> 3) & 1) * 16);

    float acc[2][8][4];
#pragma unroll
    for (int mt = 0; mt < 2; mt++)
#pragma unroll
        for (int nt = 0; nt < 8; nt++)
#pragma unroll
            for (int r = 0; r < 4; r++) acc[mt][nt][r] = 0.f;

    gemm_mainloop(Ap, Bp, sb, a_sts, b_dst, a_off, b_off, acc);

    // ---- epilogue ----
    const int g = lane >> 2, t = lane & 3;
    float cs[8][2];
    if (MODE == 1) {
#pragma unroll
        for (int nt = 0; nt < 8; nt++) { cs[nt][0] = 0.f; cs[nt][1] = 0.f; }
    }

#pragma unroll
    for (int mt = 0; mt < 2; mt++) {
        const int row0 = bm + warpM * 32 + mt * 16 + g;
        const int row1 = row0 + 8;
        int m0 = 0, m1 = 0;
        if (MODE == 2) { m0 = mask[row0]; m1 = mask[row1]; }
#pragma unroll
        for (int nt = 0; nt < 8; nt++) {
            const int col = bn + warpN * 64 + nt * 8 + t * 2;
            const float2 bv2 = *(const float2*)(bias + col);
            float v0 = acc[mt][nt][0] + bv2.x;
            float v1 = acc[mt][nt][1] + bv2.y;
            float v2 = acc[mt][nt][2] + bv2.x;
            float v3 = acc[mt][nt][3] + bv2.y;
            if (MODE == 1 || MODE == 2) {
                v0 = (v0 > 0.f) ? (v0 + 1.f) : expf(v0);
                v1 = (v1 > 0.f) ? (v1 + 1.f) : expf(v1);
                v2 = (v2 > 0.f) ? (v2 + 1.f) : expf(v2);
                v3 = (v3 > 0.f) ? (v3 + 1.f) : expf(v3);
            }
            if (MODE == 2) {
                if (m0) { v0 = 0.f; v1 = 0.f; }
                if (m1) { v2 = 0.f; v3 = 0.f; }
            }
            if (MODE == 1) {
                cs[nt][0] += v0 * v0 + v2 * v2;
                cs[nt][1] += v1 * v1 + v3 * v3;
            }
            if (MODE == 0 || MODE == 2) {
                *(uint32_t*)(Ch + (size_t)row0 * D_ + col) = h2_u32(v0, v1);
                *(uint32_t*)(Ch + (size_t)row1 * D_ + col) = h2_u32(v2, v3);
            } else {
                *(float2*)(Cf + (size_t)row0 * D_ + col) = make_float2(v0, v1);
                *(float2*)(Cf + (size_t)row1 * D_ + col) = make_float2(v2, v3);
            }
        }
    }

    if (MODE == 1) {
        const int b = bm >> 12;
#pragma unroll
        for (int nt = 0; nt < 8; nt++) {
#pragma unroll
            for (int c = 0; c < 2; c++) {
                float s = cs[nt][c];
                s += __shfl_xor_sync(0xffffffffu, s, 4);
                s += __shfl_xor_sync(0xffffffffu, s, 8);
                s += __shfl_xor_sync(0xffffffffu, s, 16);
                if (g == 0) {
                    const int col = bn + warpN * 64 + nt * 8 + t * 2 + c;
                    atomicAdd(&g_qnorm[b * D_ + col], s);
                }
            }
        }
    }
}

// ---------------------------------------------------------------------------
// weight fp16 convert (tiny: 3 x 1M elements)
// ---------------------------------------------------------------------------
__global__ void __launch_bounds__(256) cvt_w_kernel(
    const float* __restrict__ w0, const float* __restrict__ w1,
    const float* __restrict__ w2)
{
    const float* src = (blockIdx.y == 0) ? w0 : (blockIdx.y == 1) ? w1 : w2;
    const size_t i4 = (size_t)blockIdx.x * 256 + threadIdx.x;
    float4 v = ((const float4*)src)[i4];
    const size_t o = ((size_t)blockIdx.y << 20) + i4 * 4;
    *(uint2*)(g_Wh + o) = make_uint2(h2_u32(v.x, v.y), h2_u32(v.z, v.w));
}

__global__ void zero_acc_kernel()
{
    const int i = blockIdx.x * 256 + threadIdx.x;
    if (i < B_ * D_) g_qnorm[i] = 0.f;
    if (i < B_ * H_ * DH_ * DH_) g_kv[i] = 0.f;
}

// ---------------------------------------------------------------------------
// HMMA kv kernel: kv_h[d][e] += sum_n knorm(k)[n][d] * v[n][e]  (per b,h)
// grid (128 bh, 4 n-chunks of 1024); 128 threads / 4 warps; warp owns a
// 32x32 output quadrant over its chunk; atomicAdd merge across chunks.
// Both operands via ldmatrix.x4.trans from [n][feat] smem tiles.
// K rows L2-normalized in registers on the LDG path.
// ---------------------------------------------------------------------------
__global__ void __launch_bounds__(128, 1) kv_hmma_kernel()
{
    __shared__ __align__(16) __half KT[2][64][72];
    __shared__ __align__(16) __half VT[3][64][72];

    const int tid  = threadIdx.x;
    const int lane = tid & 31;
    const int wid  = tid >> 5;
    const int wm   = wid & 1;        // d-half
    const int wn   = wid >> 1;       // e-half
    const int bh   = blockIdx.x;
    const int b    = bh >> 4, h = bh & 15;
    const int nbase = blockIdx.y << 10;           // 1024-row chunk
    const size_t base = ((size_t)(b * N_ + nbase)) * D_ + (size_t)h * DH_;

    const uint32_t k0a = smem_addr_u32(&KT[0][0][0]);
    const uint32_t v0a = smem_addr_u32(&VT[0][0][0]);

    const int krow = tid >> 3;
    const int kseg = tid & 7;
    const int vrow = tid >> 1;
    const int vp   = tid & 1;

    const uint32_t a_toff = (uint32_t)(((lane & 7) + ((lane >> 4) & 1) * 8) * 144
                                       + wm * 64 + ((lane >> 3) & 1) * 16);
    const uint32_t b_toff = (uint32_t)(((lane & 7) + ((lane >> 3) & 1) * 8) * 144
                                       + wn * 64 + ((lane >> 4) & 1) * 16);

    float acc[2][4][4];
#pragma unroll
    for (int mi = 0; mi < 2; mi++)
#pragma unroll
        for (int ni = 0; ni < 4; ni++)
#pragma unroll
            for (int r = 0; r < 4; r++) acc[mi][ni][r] = 0.f;

    uint4 kr[4];

    // ---- prologue ----
#pragma unroll
    for (int st = 0; st < 2; st++) {
        const uint32_t vd = v0a + (uint32_t)st * 9216u
                          + (uint32_t)(vrow * 144 + vp * 64);
        const __half* gv = g_Vh + base + (size_t)(st * 64 + vrow) * D_ + vp * 32;
#pragma unroll
        for (int c = 0; c < 4; c++)
            CP_ASYNC16(vd + c * 16u, gv + c * 8);
        CP_COMMIT();
    }
#pragma unroll
    for (int i = 0; i < 4; i++)
        kr[i] = *(const uint4*)(g_Kh + base + (size_t)(krow + 16 * i) * D_ + kseg * 8);
#pragma unroll
    for (int i = 0; i < 4; i++) {
        float f[8];
        const __half2* hp = (const __half2*)&kr[i];
#pragma unroll
        for (int j = 0; j < 4; j++) {
            float2 fp = __half22float2(hp[j]);
            f[2 * j] = fp.x; f[2 * j + 1] = fp.y;
        }
        float s = 0.f;
#pragma unroll
        for (int j = 0; j < 8; j++) s += f[j] * f[j];
        s += __shfl_xor_sync(0xffffffffu, s, 1);
        s += __shfl_xor_sync(0xffffffffu, s, 2);
        s += __shfl_xor_sync(0xffffffffu, s, 4);
        const float inv = 1.0f / fmaxf(sqrtf(s), 1e-12f);
        uint4 packed;
        packed.x = h2_u32(f[0] * inv, f[1] * inv);
        packed.y = h2_u32(f[2] * inv, f[3] * inv);
        packed.z = h2_u32(f[4] * inv, f[5] * inv);
        packed.w = h2_u32(f[6] * inv, f[7] * inv);
        sts_b128(k0a + (uint32_t)((krow + 16 * i) * 144 + kseg * 16), packed);
    }
#pragma unroll
    for (int i = 0; i < 4; i++)
        kr[i] = *(const uint4*)(g_Kh + base + (size_t)(64 + krow + 16 * i) * D_ + kseg * 8);

    int vs = 0;   // t % 3
#pragma unroll 1
    for (int t = 0; t < 16; t++) {
        CP_WAIT1();
        __syncthreads();

        if (t < 15) {
            const uint32_t kb = k0a + (uint32_t)((t + 1) & 1) * 9216u;
#pragma unroll
            for (int i = 0; i < 4; i++) {
                float f[8];
                const __half2* hp = (const __half2*)&kr[i];
#pragma unroll
                for (int j = 0; j < 4; j++) {
                    float2 fp = __half22float2(hp[j]);
                    f[2 * j] = fp.x; f[2 * j + 1] = fp.y;
                }
                float s = 0.f;
#pragma unroll
                for (int j = 0; j < 8; j++) s += f[j] * f[j];
                s += __shfl_xor_sync(0xffffffffu, s, 1);
                s += __shfl_xor_sync(0xffffffffu, s, 2);
                s += __shfl_xor_sync(0xffffffffu, s, 4);
                const float inv = 1.0f / fmaxf(sqrtf(s), 1e-12f);
                uint4 packed;
                packed.x = h2_u32(f[0] * inv, f[1] * inv);
                packed.y = h2_u32(f[2] * inv, f[3] * inv);
                packed.z = h2_u32(f[4] * inv, f[5] * inv);
                packed.w = h2_u32(f[6] * inv, f[7] * inv);
                sts_b128(kb + (uint32_t)((krow + 16 * i) * 144 + kseg * 16), packed);
            }
        }
        if (t + 2 < 16) {
            const int n2 = (t + 2) * 64;
#pragma unroll
            for (int i = 0; i < 4; i++)
                kr[i] = *(const uint4*)(g_Kh + base + (size_t)(n2 + krow + 16 * i) * D_ + kseg * 8);
            const int vs2 = (vs + 2 >= 3) ? vs - 1 : vs + 2;
            const uint32_t vd = v0a + (uint32_t)vs2 * 9216u
                              + (uint32_t)(vrow * 144 + vp * 64);
            const __half* gv = g_Vh + base + (size_t)(n2 + vrow) * D_ + vp * 32;
#pragma unroll
            for (int c = 0; c < 4; c++)
                CP_ASYNC16(vd + c * 16u, gv + c * 8);
        }
        CP_COMMIT();

        const uint32_t ka = k0a + (uint32_t)(t & 1) * 9216u;
        const uint32_t va = v0a + (uint32_t)vs * 9216u;
#pragma unroll
        for (int k16 = 0; k16 < 4; k16++) {
            const uint32_t nb = (uint32_t)(k16 * 16 * 144);
            uint32_t a0[4], a1[4], bv0[4], bv1[4];
            LDSM4T(a0, ka + a_toff + nb);
            LDSM4T(a1, ka + a_toff + nb + 32u);
            LDSM4T(bv0, va + b_toff + nb);
            LDSM4T(bv1, va + b_toff + nb + 32u);
            mma16816h(acc[0][0], a0, bv0);
            mma16816h(acc[0][1], a0, bv0 + 2);
            mma16816h(acc[0][2], a0, bv1);
            mma16816h(acc[0][3], a0, bv1 + 2);
            mma16816h(acc[1][0], a1, bv0);
            mma16816h(acc[1][1], a1, bv0 + 2);
            mma16816h(acc[1][2], a1, bv1);
            mma16816h(acc[1][3], a1, bv1 + 2);
        }
        vs = (vs + 1 >= 3) ? 0 : vs + 1;
    }

    // ---- merge across n-chunks ----
    const int g = lane >> 2, tq = lane & 3;
    float* outp = g_kv + (size_t)bh * (DH_ * DH_);
#pragma unroll
    for (int mi = 0; mi < 2; mi++) {
        const int d0 = wm * 32 + mi * 16 + g;
#pragma unroll
        for (int ni = 0; ni < 4; ni++) {
            const int e = wn * 32 + ni * 8 + tq * 2;
            atomicAdd(outp + (d0)     * DH_ + e,     acc[mi][ni][0]);
            atomicAdd(outp + (d0)     * DH_ + e + 1, acc[mi][ni][1]);
            atomicAdd(outp + (d0 + 8) * DH_ + e,     acc[mi][ni][2]);
            atomicAdd(outp + (d0 + 8) * DH_ + e + 1, acc[mi][ni][3]);
        }
    }
}

// ---------------------------------------------------------------------------
// GT_b[j][h*64+d] = (sum_e kv[b,h][d][e] * Wo[j][h*64+e]) / max(sqrt(qn),eps)
// emitted fp16.
// ---------------------------------------------------------------------------
__global__ void __launch_bounds__(256) gt_kernel(const float* __restrict__ Wo)
{
    __shared__ __align__(16) float kvs[64][65];
    __shared__ __align__(16) float Wos[64][65];
    const int tid = threadIdx.x;
    const int jt = blockIdx.x, h = blockIdx.y, b = blockIdx.z;
    const float* kvp = g_kv + (size_t)(b * H_ + h) * (DH_ * DH_);

#pragma unroll
    for (int i = 0; i < 16; i++) {
        const int idx = tid + (i << 8);
        const int r = idx >> 6, e = idx & 63;
        kvs[r][e] = kvp[idx];
        Wos[r][e] = Wo[(size_t)(jt * 64 + r) * D_ + h * 64 + e];
    }
    __syncthreads();

    const int tj = (tid >> 4) << 2;
    const int td = (tid & 15) << 2;
    float acc[4][4];
#pragma unroll
    for (int i = 0; i < 4; i++)
#pragma unroll
        for (int j = 0; j < 4; j++) acc[i][j] = 0.f;

#pragma unroll 16
    for (int e = 0; e < 64; e++) {
        float wv[4], kvv[4];
#pragma unroll
        for (int i = 0; i < 4; i++) { wv[i] = Wos[tj + i][e]; kvv[i] = kvs[td + i][e]; }
#pragma unroll
        for (int i = 0; i < 4; i++)
#pragma unroll
            for (int j = 0; j < 4; j++)
                acc[i][j] = fmaf(wv[i], kvv[j], acc[i][j]);
    }

    float sc[4];
#pragma unroll
    for (int j = 0; j < 4; j++)
        sc[j] = 1.0f / fmaxf(sqrtf(g_qnorm[b * D_ + h * 64 + td + j]), 1e-12f);

    const size_t ob = ((size_t)b << 20) + (size_t)(jt * 64 + tj) * D_ + h * 64 + td;
#pragma unroll
    for (int i = 0; i < 4; i++)
        *(uint2*)(g_GTh + ob + (size_t)i * D_) =
            make_uint2(h2_u32(acc[i][0] * sc[0], acc[i][1] * sc[1]),
                       h2_u32(acc[i][2] * sc[2], acc[i][3] * sc[3]));
}

// ---------------------------------------------------------------------------
extern "C" void kernel_launch(void* const* d_in, const int* in_sizes, int n_in,
                              void* d_out, int out_size)
{
    (void)in_sizes; (void)n_in; (void)out_size;
    const float* query = (const float*)d_in[0];
    const float* key   = (const float*)d_in[1];
    const float* value = (const float*)d_in[2];
    const int*   mask  = (const int*)d_in[3];   // bool materialized as int32
    const float* Wq = (const float*)d_in[4];
    const float* bq = (const float*)d_in[5];
    const float* Wk = (const float*)d_in[6];
    const float* bk = (const float*)d_in[7];
    const float* Wv = (const float*)d_in[8];
    const float* bv = (const float*)d_in[9];
    const float* Wo = (const float*)d_in[10];
    const float* bo = (const float*)d_in[11];
    float* out = (float*)d_out;

    __half *Wh, *GTh, *Kh, *Vh;
    float *Q;
    cudaGetSymbolAddress((void**)&Wh,  g_Wh);
    cudaGetSymbolAddress((void**)&GTh, g_GTh);
    cudaGetSymbolAddress((void**)&Kh,  g_Kh);
    cudaGetSymbolAddress((void**)&Vh,  g_Vh);
    cudaGetSymbolAddress((void**)&Q,   g_Q);

    cudaFuncSetAttribute(gemm_fp16<0>, cudaFuncAttributeMaxDynamicSharedMemorySize, GEMM_SMEM);
    cudaFuncSetAttribute(gemm_fp16<1>, cudaFuncAttributeMaxDynamicSharedMemorySize, GEMM_SMEM);
    cudaFuncSetAttribute(gemm_fp16<2>, cudaFuncAttributeMaxDynamicSharedMemorySize, GEMM_SMEM);
    cudaFuncSetAttribute(gemm_fp16<3>, cudaFuncAttributeMaxDynamicSharedMemorySize, GEMM_SMEM);

    const size_t WN = (size_t)D_ * D_;

    dim3 gblk(256);
    dim3 ggrid(D_ / 128, M_ / 128);      // (8, 256)

    cvt_w_kernel<<<dim3(1024, 3), 256>>>(Wq, Wk, Wv);
    zero_acc_kernel<<<(B_ * H_ * DH_ * DH_ + 255) / 256, 256>>>();

    gemm_fp16<1><<<ggrid, gblk, GEMM_SMEM>>>(query, Wh,          bq, nullptr, Q,       nullptr);
    gemm_fp16<2><<<ggrid, gblk, GEMM_SMEM>>>(key,   Wh + WN,     bk, mask,    nullptr, Kh);
    gemm_fp16<0><<<ggrid, gblk, GEMM_SMEM>>>(value, Wh + 2 * WN, bv, nullptr, nullptr, Vh);

    kv_hmma_kernel<<<dim3(B_ * H_, 4), 128>>>();
    gt_kernel<<<dim3(16, 16, 8), 256>>>(Wo);

    gemm_fp16<3><<<ggrid, gblk, GEMM_SMEM>>>(Q, GTh, bo, nullptr, out, nullptr);
}